// round 8
// baseline (speedup 1.0000x reference)
#include <cuda_runtime.h>
#include <cuda_fp16.h>
#include <cstdint>

#define Nn   100000
#define Ee   1600000
#define INF  128
#define HID  64
#define OUTF 40
#define NB   ((Nn + 255) / 256)          // 391 node blocks
#define GB   ((Nn + 63) / 64)            // 1563 gemm tiles
#define EB   ((Ee + 255) / 256)          // 6250 edge blocks
#define AGGB 1184                        // one full wave of agg blocks

// ---------------- scratch (static device globals: allocation-free) ----------
__device__ __half2 g_h  [(size_t)Nn * (HID / 2)];  // x @ W1, fp16
__device__ __half2 g_agg[(size_t)Nn * (HID / 2)];  // BN input, fp16
__device__ __half  g_h2 [(size_t)Nn * OUTF];       // relu(bn(h)) @ W2, fp16
__device__ __half  g_W1t[HID][INF];                // W1 transposed [n][k], fp16
__device__ float   g_dinv [Nn];
__device__ int     g_degi [Nn];
__device__ int2    g_row2 [Nn];                    // {rowstart, degree}
__device__ unsigned short g_rank[Ee];              // edge rank within dst row
__device__ int     g_ctr;
__device__ float   g_sum  [HID];
__device__ float   g_sqsum[HID];
__device__ int4    g_ecsr_raw[(Ee + 1) / 2];       // 16B-aligned backing
#define g_ecsr ((int2*)g_ecsr_raw)
__device__ int     g_is64;

// ---------------- zero accumulators + dtype probe + W1 fp16 transpose -------
__global__ void __launch_bounds__(256) zero_kernel(const int* __restrict__ w,
                                                   const float* __restrict__ W1) {
    int i = blockIdx.x * 256 + threadIdx.x;
    if (i < Nn) g_degi[i] = 0;
    if (i < HID) { g_sum[i] = 0.f; g_sqsum[i] = 0.f; }
    if (i < INF * HID) {
        int n = i >> 7, k = i & 127;
        g_W1t[n][k] = __float2half_rn(W1[(size_t)k * HID + n]);
    }
    if (blockIdx.x == 0 && threadIdx.x == 0) {
        int is64 = 1;
        #pragma unroll
        for (int k = 1; k < 64; k += 2) is64 &= (w[k] == 0);
        g_is64 = is64;
        g_ctr = 0;
    }
}

// ---------------- fp16 mma helper -------------------------------------------
__device__ __forceinline__ void mma_f16(float* d, uint32_t a0, uint32_t a1,
                                        uint32_t a2, uint32_t a3,
                                        uint32_t b0, uint32_t b1) {
    asm volatile(
        "mma.sync.aligned.m16n8k16.row.col.f32.f16.f16.f32 "
        "{%0,%1,%2,%3}, {%4,%5,%6,%7}, {%8,%9}, {%0,%1,%2,%3};"
        : "+f"(d[0]), "+f"(d[1]), "+f"(d[2]), "+f"(d[3])
        : "r"(a0), "r"(a1), "r"(a2), "r"(a3), "r"(b0), "r"(b1));
}

// ---------------- fused: GEMM1 (fp16 mma) + degree histogram + edge ranks ---
// bid % 5 == 0 -> gemm tile (bid/5), else histogram block.
__global__ void __launch_bounds__(256) fused1_kernel(const void* __restrict__ ei_raw,
                                                     const float* __restrict__ x) {
    __shared__ __half xh [64][136];
    __shared__ __half whT[64][136];
    int bid = blockIdx.x;
    int q = bid / 5, r = bid - q * 5;
    int tid = threadIdx.x;

    if (r != 0) {
        int e = (q * 4 + (r - 1)) * 256 + tid;
        if (e < Ee) {
            int d;
            if (g_is64) d = (int)((const long long*)ei_raw)[Ee + e];
            else        d = ((const int*)ei_raw)[Ee + e];
            int old = atomicAdd(&g_degi[d], 1);
            g_rank[e] = (unsigned short)old;       // rank within dst row
        }
        return;
    }

    // ---- gemm tile: 64 nodes x 64 cols, K=128, one pass ----
    int base = q * 64;
    int lane = tid & 31, w = tid >> 5;
    int wr = (w & 3) * 16;
    int wc = (w >> 2) * 32;
    int g  = lane >> 2, t = lane & 3;

    #pragma unroll
    for (int f = 0; f < 8; f++) {
        int fi  = f * 256 + tid;
        int row = fi >> 5, kb = (fi & 31) << 2;
        float4 v = {0.f, 0.f, 0.f, 0.f};
        if (base + row < Nn) v = *(const float4*)(x + (size_t)(base + row) * INF + kb);
        __half2* dst = (__half2*)&xh[row][kb];
        dst[0] = __floats2half2_rn(v.x, v.y);
        dst[1] = __floats2half2_rn(v.z, v.w);
    }
    #pragma unroll
    for (int f = 0; f < 4; f++) {
        int fi = f * 256 + tid;
        int n = fi >> 4, kb = (fi & 15) << 3;
        *(int4*)&whT[n][kb] = *(const int4*)&g_W1t[n][kb];
    }
    __syncthreads();

    float acc[4][4] = {};
    #pragma unroll
    for (int ks = 0; ks < INF; ks += 16) {
        uint32_t a0 = *(const uint32_t*)&xh[wr + g    ][ks + 2 * t    ];
        uint32_t a1 = *(const uint32_t*)&xh[wr + g + 8][ks + 2 * t    ];
        uint32_t a2 = *(const uint32_t*)&xh[wr + g    ][ks + 2 * t + 8];
        uint32_t a3 = *(const uint32_t*)&xh[wr + g + 8][ks + 2 * t + 8];
        #pragma unroll
        for (int j = 0; j < 4; j++) {
            int n0 = wc + 8 * j;
            uint32_t b0 = *(const uint32_t*)&whT[n0 + g][ks + 2 * t    ];
            uint32_t b1 = *(const uint32_t*)&whT[n0 + g][ks + 2 * t + 8];
            mma_f16(acc[j], a0, a1, a2, a3, b0, b1);
        }
    }
    #pragma unroll
    for (int j = 0; j < 4; j++) {
        int hc = (wc + 8 * j) / 2 + t;
        int r0 = base + wr + g;
        int r1 = r0 + 8;
        if (r0 < Nn) g_h[(size_t)r0 * (HID / 2) + hc] = __floats2half2_rn(acc[j][0], acc[j][1]);
        if (r1 < Nn) g_h[(size_t)r1 * (HID / 2) + hc] = __floats2half2_rn(acc[j][2], acc[j][3]);
    }
}

// ---------------- prep: unordered CSR row assignment + dinv -----------------
__global__ void __launch_bounds__(256) prep_kernel() {
    int i = blockIdx.x * 256 + threadIdx.x;
    int tid = threadIdx.x;
    int d = (i < Nn) ? g_degi[i] : 0;
    int lane = tid & 31, wid = tid >> 5;
    int v = d;
    #pragma unroll
    for (int o = 1; o < 32; o <<= 1) {
        int u = __shfl_up_sync(0xffffffffu, v, o);
        if (lane >= o) v += u;
    }
    __shared__ int wsum[8];
    __shared__ int sbase;
    if (lane == 31) wsum[wid] = v;
    __syncthreads();
    if (tid < 8) {
        int u = wsum[tid];
        #pragma unroll
        for (int o = 1; o < 8; o <<= 1) {
            int t2 = __shfl_up_sync(0xffu, u, o);
            if (tid >= o) u += t2;
        }
        wsum[tid] = u;
        if (tid == 7) sbase = atomicAdd(&g_ctr, u);
    }
    __syncthreads();
    int inc = v + (wid > 0 ? wsum[wid - 1] : 0);
    if (i < Nn) {
        int st = sbase + inc - d;
        g_row2[i] = make_int2(st, d);
        g_dinv[i] = rsqrtf((float)d + 1.0f);
    }
}

// ---------------- scatter edges into CSR (atomic-free via ranks) ------------
__global__ void __launch_bounds__(256) scatter_kernel(const void* __restrict__ ei_raw) {
    int e = blockIdx.x * 256 + threadIdx.x;
    if (e >= Ee) return;
    int s, d;
    if (g_is64) {
        const long long* p = (const long long*)ei_raw;
        s = (int)p[e]; d = (int)p[Ee + e];
    } else {
        const int* p = (const int*)ei_raw;
        s = p[e]; d = p[Ee + e];
    }
    int pos = g_row2[d].x + (int)g_rank[e];
    g_ecsr[pos] = make_int2(s, __float_as_int(g_dinv[s] * g_dinv[d]));
}

// ---------------- layer-1 CSR aggregation + self-loop + b1 + BN stats -------
__device__ __forceinline__ void eacc1(int sv, float cf, int lane, float& ax, float& ay) {
    float2 h = __half22float2(g_h[(size_t)sv * (HID / 2) + lane]);
    ax = fmaf(h.x, cf, ax); ay = fmaf(h.y, cf, ay);
}

__global__ void __launch_bounds__(256) agg1_csr_kernel(const float* __restrict__ b1) {
    int lane = threadIdx.x & 31;
    int warp = (blockIdx.x * 256 + threadIdx.x) >> 5;
    int nw   = (gridDim.x * 256) >> 5;
    float2 bb = *(const float2*)(b1 + 2 * lane);
    float2 sum = {0.f, 0.f}, sq = {0.f, 0.f};

    for (int n = warp; n < Nn; n += nw) {
        int2 rd = g_row2[n];
        int rs = rd.x, re = rd.x + rd.y;
        float ax = 0.f, ay = 0.f;
        int j = rs;
        if ((j & 1) && j < re) {
            int2 e = g_ecsr[j];
            eacc1(e.x, __int_as_float(e.y), lane, ax, ay);
            j++;
        }
        for (; j + 7 < re; j += 8) {
            int4 A = *(const int4*)(g_ecsr + j);
            int4 B = *(const int4*)(g_ecsr + j + 2);
            int4 C = *(const int4*)(g_ecsr + j + 4);
            int4 D = *(const int4*)(g_ecsr + j + 6);
            eacc1(A.x, __int_as_float(A.y), lane, ax, ay);
            eacc1(A.z, __int_as_float(A.w), lane, ax, ay);
            eacc1(B.x, __int_as_float(B.y), lane, ax, ay);
            eacc1(B.z, __int_as_float(B.w), lane, ax, ay);
            eacc1(C.x, __int_as_float(C.y), lane, ax, ay);
            eacc1(C.z, __int_as_float(C.w), lane, ax, ay);
            eacc1(D.x, __int_as_float(D.y), lane, ax, ay);
            eacc1(D.z, __int_as_float(D.w), lane, ax, ay);
        }
        for (; j + 3 < re; j += 4) {
            int4 A = *(const int4*)(g_ecsr + j);
            int4 B = *(const int4*)(g_ecsr + j + 2);
            eacc1(A.x, __int_as_float(A.y), lane, ax, ay);
            eacc1(A.z, __int_as_float(A.w), lane, ax, ay);
            eacc1(B.x, __int_as_float(B.y), lane, ax, ay);
            eacc1(B.z, __int_as_float(B.w), lane, ax, ay);
        }
        if (j + 1 < re) {
            int4 A = *(const int4*)(g_ecsr + j);
            eacc1(A.x, __int_as_float(A.y), lane, ax, ay);
            eacc1(A.z, __int_as_float(A.w), lane, ax, ay);
            j += 2;
        }
        if (j < re) {
            int2 e = g_ecsr[j];
            eacc1(e.x, __int_as_float(e.y), lane, ax, ay);
        }
        float dv = g_dinv[n];
        float sl = dv * dv;
        float2 hn = __half22float2(g_h[(size_t)n * (HID / 2) + lane]);
        float vx = ax + hn.x * sl + bb.x;
        float vy = ay + hn.y * sl + bb.y;
        g_agg[(size_t)n * (HID / 2) + lane] = __floats2half2_rn(vx, vy);
        sum.x += vx; sum.y += vy;
        sq.x  += vx * vx; sq.y += vy * vy;
    }

    __shared__ float ss[HID], sqs[HID];
    if (threadIdx.x < HID) { ss[threadIdx.x] = 0.f; sqs[threadIdx.x] = 0.f; }
    __syncthreads();
    atomicAdd(&ss [2 * lane],     sum.x);
    atomicAdd(&ss [2 * lane + 1], sum.y);
    atomicAdd(&sqs[2 * lane],     sq.x);
    atomicAdd(&sqs[2 * lane + 1], sq.y);
    __syncthreads();
    if (threadIdx.x < HID)          atomicAdd(&g_sum  [threadIdx.x],       ss [threadIdx.x]);
    else if (threadIdx.x < 2 * HID) atomicAdd(&g_sqsum[threadIdx.x - HID], sqs[threadIdx.x - HID]);
}

// ---------------- GEMM2 with inline BN-final + ReLU -------------------------
__global__ void __launch_bounds__(256) gemm2_kernel(const float* __restrict__ W2,
                                                    const float* __restrict__ gamma,
                                                    const float* __restrict__ beta) {
    __shared__ float yst[HID][68];
    __shared__ float ws [HID * OUTF];
    __shared__ float scale[HID], shift[HID];
    int tid  = threadIdx.x;
    int base = blockIdx.x * 64;
    const __half* aggh = (const __half*)g_agg;

    if (tid < HID) {
        float mean = g_sum[tid]   * (1.0f / Nn);
        float var  = g_sqsum[tid] * (1.0f / Nn) - mean * mean;
        float sc   = gamma[tid] * rsqrtf(var + 1e-5f);
        scale[tid] = sc;
        shift[tid] = beta[tid] - mean * sc;
    }
    for (int i = tid; i < HID * OUTF; i += 256) ws[i] = W2[i];
    __syncthreads();
    for (int i = tid; i < 64 * 64; i += 256) {
        int node = i >> 6, k = i & 63;
        int row = base + node;
        float v = 0.f;
        if (row < Nn) {
            v = __half2float(aggh[(size_t)row * HID + k]);
            v = fmaxf(v * scale[k] + shift[k], 0.f);
        }
        yst[k][node] = v;
    }
    __syncthreads();

    int ng = tid >> 3;
    int cg = (tid & 7) * 5;
    float acc0[5] = {}, acc1[5] = {};
    #pragma unroll 8
    for (int k = 0; k < HID; k++) {
        float2 yv = *(const float2*)&yst[k][ng * 2];
        #pragma unroll
        for (int j = 0; j < 5; j++) {
            float w = ws[k * OUTF + cg + j];
            acc0[j] += yv.x * w;
            acc1[j] += yv.y * w;
        }
    }
    int r0 = base + ng * 2;
    if (r0 < Nn) {
        #pragma unroll
        for (int j = 0; j < 5; j++)
            g_h2[(size_t)r0 * OUTF + cg + j] = __float2half_rn(acc0[j]);
    }
    if (r0 + 1 < Nn) {
        #pragma unroll
        for (int j = 0; j < 5; j++)
            g_h2[(size_t)(r0 + 1) * OUTF + cg + j] = __float2half_rn(acc1[j]);
    }
}

// ---------------- layer-2 CSR aggregation + self-loop + b2 → d_out ----------
__device__ __forceinline__ void eacc2(int sv, float cf, int lane, float& ax, float& ay) {
    float2 h = __half22float2(*(const __half2*)(g_h2 + (size_t)sv * OUTF + 2 * lane));
    ax = fmaf(h.x, cf, ax); ay = fmaf(h.y, cf, ay);
}

__global__ void __launch_bounds__(256) agg2_csr_kernel(const float* __restrict__ b2,
                                                       float* __restrict__ out) {
    int lane = threadIdx.x & 31;
    int warp = (blockIdx.x * 256 + threadIdx.x) >> 5;
    int nw   = (gridDim.x * 256) >> 5;
    if (lane >= OUTF / 2) return;
    float2 bb = *(const float2*)(b2 + 2 * lane);

    for (int n = warp; n < Nn; n += nw) {
        int2 rd = g_row2[n];
        int rs = rd.x, re = rd.x + rd.y;
        float ax = 0.f, ay = 0.f;
        int j = rs;
        if ((j & 1) && j < re) {
            int2 e = g_ecsr[j];
            eacc2(e.x, __int_as_float(e.y), lane, ax, ay);
            j++;
        }
        for (; j + 7 < re; j += 8) {
            int4 A = *(const int4*)(g_ecsr + j);
            int4 B = *(const int4*)(g_ecsr + j + 2);
            int4 C = *(const int4*)(g_ecsr + j + 4);
            int4 D = *(const int4*)(g_ecsr + j + 6);
            eacc2(A.x, __int_as_float(A.y), lane, ax, ay);
            eacc2(A.z, __int_as_float(A.w), lane, ax, ay);
            eacc2(B.x, __int_as_float(B.y), lane, ax, ay);
            eacc2(B.z, __int_as_float(B.w), lane, ax, ay);
            eacc2(C.x, __int_as_float(C.y), lane, ax, ay);
            eacc2(C.z, __int_as_float(C.w), lane, ax, ay);
            eacc2(D.x, __int_as_float(D.y), lane, ax, ay);
            eacc2(D.z, __int_as_float(D.w), lane, ax, ay);
        }
        for (; j + 3 < re; j += 4) {
            int4 A = *(const int4*)(g_ecsr + j);
            int4 B = *(const int4*)(g_ecsr + j + 2);
            eacc2(A.x, __int_as_float(A.y), lane, ax, ay);
            eacc2(A.z, __int_as_float(A.w), lane, ax, ay);
            eacc2(B.x, __int_as_float(B.y), lane, ax, ay);
            eacc2(B.z, __int_as_float(B.w), lane, ax, ay);
        }
        if (j + 1 < re) {
            int4 A = *(const int4*)(g_ecsr + j);
            eacc2(A.x, __int_as_float(A.y), lane, ax, ay);
            eacc2(A.z, __int_as_float(A.w), lane, ax, ay);
            j += 2;
        }
        if (j < re) {
            int2 e = g_ecsr[j];
            eacc2(e.x, __int_as_float(e.y), lane, ax, ay);
        }
        float dv = g_dinv[n];
        float sl = dv * dv;
        float2 hn = __half22float2(*(const __half2*)(g_h2 + (size_t)n * OUTF + 2 * lane));
        float2 v = {ax + hn.x * sl + bb.x, ay + hn.y * sl + bb.y};
        *(float2*)(out + (size_t)n * OUTF + 2 * lane) = v;
    }
}

// ---------------- launch ----------------------------------------------------
extern "C" void kernel_launch(void* const* d_in, const int* in_sizes, int n_in,
                              void* d_out, int out_size) {
    const float* x     = (const float*)d_in[0];
    const void*  ei    = d_in[1];
    const float* W1    = (const float*)d_in[2];
    const float* b1    = (const float*)d_in[3];
    const float* gamma = (const float*)d_in[4];
    const float* beta  = (const float*)d_in[5];
    const float* W2    = (const float*)d_in[6];
    const float* b2    = (const float*)d_in[7];
    float* out = (float*)d_out;

    zero_kernel<<<NB, 256>>>((const int*)ei, W1);
    fused1_kernel<<<GB * 5, 256>>>(ei, x);        // gemm1 + histogram + ranks
    prep_kernel<<<NB, 256>>>();
    scatter_kernel<<<EB, 256>>>(ei);              // atomic-free
    agg1_csr_kernel<<<AGGB, 256>>>(b1);
    gemm2_kernel<<<GB, 256>>>(W2, gamma, beta);
    agg2_csr_kernel<<<AGGB, 256>>>(b2, out);
}

// round 9
// speedup vs baseline: 1.0819x; 1.0819x over previous
#include <cuda_runtime.h>
#include <cuda_fp16.h>
#include <cstdint>

#define Nn   100000
#define Ee   1600000
#define INF  128
#define HID  64
#define OUTF 40
#define NB   ((Nn + 255) / 256)          // 391 node blocks
#define GB   ((Nn + 63) / 64)            // 1563 gemm tiles
#define EB   ((Ee + 255) / 256)          // 6250 edge blocks
#define AGGB 1184                        // one full wave of agg blocks

// ---------------- scratch (static device globals: allocation-free) ----------
__device__ __half2 g_h  [(size_t)Nn * (HID / 2)];  // x @ W1, pre-scaled by dinv
__device__ __half2 g_agg[(size_t)Nn * (HID / 2)];  // BN input, fp16
__device__ __half  g_h2 [(size_t)Nn * OUTF];       // relu(bn)@W2, pre-scaled
__device__ __half  g_W1t[HID][INF];                // W1 transposed [n][k], fp16
__device__ float   g_dinv [Nn];
__device__ int     g_degi [Nn];
__device__ int2    g_row2 [Nn];                    // {rowstart, degree}
__device__ int     g_cursor[Nn];
__device__ int     g_ctr;
__device__ float   g_sum  [HID];
__device__ float   g_sqsum[HID];
__device__ int4    g_e4[(Ee + 3) / 4];             // 16B-aligned CSR src indices
#define g_ecsr4 ((int*)g_e4)
__device__ int     g_is64;

// ---------------- zero accumulators + dtype probe + W1 fp16 transpose -------
__global__ void __launch_bounds__(256) zero_kernel(const int* __restrict__ w,
                                                   const float* __restrict__ W1) {
    int i = blockIdx.x * 256 + threadIdx.x;
    if (i < Nn) g_degi[i] = 0;
    if (i < HID) { g_sum[i] = 0.f; g_sqsum[i] = 0.f; }
    if (i < INF * HID) {
        int n = i >> 7, k = i & 127;
        g_W1t[n][k] = __float2half_rn(W1[(size_t)k * HID + n]);
    }
    if (blockIdx.x == 0 && threadIdx.x == 0) {
        int is64 = 1;
        #pragma unroll
        for (int k = 1; k < 64; k += 2) is64 &= (w[k] == 0);
        g_is64 = is64;
        g_ctr = 0;
    }
}

// ---------------- fp16 mma helper -------------------------------------------
__device__ __forceinline__ void mma_f16(float* d, uint32_t a0, uint32_t a1,
                                        uint32_t a2, uint32_t a3,
                                        uint32_t b0, uint32_t b1) {
    asm volatile(
        "mma.sync.aligned.m16n8k16.row.col.f32.f16.f16.f32 "
        "{%0,%1,%2,%3}, {%4,%5,%6,%7}, {%8,%9}, {%0,%1,%2,%3};"
        : "+f"(d[0]), "+f"(d[1]), "+f"(d[2]), "+f"(d[3])
        : "r"(a0), "r"(a1), "r"(a2), "r"(a3), "r"(b0), "r"(b1));
}

// ---------------- fused: GEMM1 (fp16 mma) + degree histogram ----------------
// bid % 5 == 0 -> gemm tile (bid/5), else histogram block (fire-and-forget RED).
__global__ void __launch_bounds__(256) fused1_kernel(const void* __restrict__ ei_raw,
                                                     const float* __restrict__ x) {
    __shared__ __half xh [64][136];
    __shared__ __half whT[64][136];
    int bid = blockIdx.x;
    int q = bid / 5, r = bid - q * 5;
    int tid = threadIdx.x;

    if (r != 0) {
        int e = (q * 4 + (r - 1)) * 256 + tid;
        if (e < Ee) {
            int d;
            if (g_is64) d = (int)((const long long*)ei_raw)[Ee + e];
            else        d = ((const int*)ei_raw)[Ee + e];
            atomicAdd(&g_degi[d], 1);
        }
        return;
    }

    int base = q * 64;
    int lane = tid & 31, w = tid >> 5;
    int wr = (w & 3) * 16;
    int wc = (w >> 2) * 32;
    int g  = lane >> 2, t = lane & 3;

    #pragma unroll
    for (int f = 0; f < 8; f++) {
        int fi  = f * 256 + tid;
        int row = fi >> 5, kb = (fi & 31) << 2;
        float4 v = {0.f, 0.f, 0.f, 0.f};
        if (base + row < Nn) v = *(const float4*)(x + (size_t)(base + row) * INF + kb);
        __half2* dst = (__half2*)&xh[row][kb];
        dst[0] = __floats2half2_rn(v.x, v.y);
        dst[1] = __floats2half2_rn(v.z, v.w);
    }
    #pragma unroll
    for (int f = 0; f < 4; f++) {
        int fi = f * 256 + tid;
        int n = fi >> 4, kb = (fi & 15) << 3;
        *(int4*)&whT[n][kb] = *(const int4*)&g_W1t[n][kb];
    }
    __syncthreads();

    float acc[4][4] = {};
    #pragma unroll
    for (int ks = 0; ks < INF; ks += 16) {
        uint32_t a0 = *(const uint32_t*)&xh[wr + g    ][ks + 2 * t    ];
        uint32_t a1 = *(const uint32_t*)&xh[wr + g + 8][ks + 2 * t    ];
        uint32_t a2 = *(const uint32_t*)&xh[wr + g    ][ks + 2 * t + 8];
        uint32_t a3 = *(const uint32_t*)&xh[wr + g + 8][ks + 2 * t + 8];
        #pragma unroll
        for (int j = 0; j < 4; j++) {
            int n0 = wc + 8 * j;
            uint32_t b0 = *(const uint32_t*)&whT[n0 + g][ks + 2 * t    ];
            uint32_t b1 = *(const uint32_t*)&whT[n0 + g][ks + 2 * t + 8];
            mma_f16(acc[j], a0, a1, a2, a3, b0, b1);
        }
    }
    #pragma unroll
    for (int j = 0; j < 4; j++) {
        int hc = (wc + 8 * j) / 2 + t;
        int r0 = base + wr + g;
        int r1 = r0 + 8;
        if (r0 < Nn) g_h[(size_t)r0 * (HID / 2) + hc] = __floats2half2_rn(acc[j][0], acc[j][1]);
        if (r1 < Nn) g_h[(size_t)r1 * (HID / 2) + hc] = __floats2half2_rn(acc[j][2], acc[j][3]);
    }
}

// ---------------- prep: unordered CSR row assignment + dinv -----------------
__global__ void __launch_bounds__(256) prep_kernel() {
    int i = blockIdx.x * 256 + threadIdx.x;
    int tid = threadIdx.x;
    int d = (i < Nn) ? g_degi[i] : 0;
    int lane = tid & 31, wid = tid >> 5;
    int v = d;
    #pragma unroll
    for (int o = 1; o < 32; o <<= 1) {
        int u = __shfl_up_sync(0xffffffffu, v, o);
        if (lane >= o) v += u;
    }
    __shared__ int wsum[8];
    __shared__ int sbase;
    if (lane == 31) wsum[wid] = v;
    __syncthreads();
    if (tid < 8) {
        int u = wsum[tid];
        #pragma unroll
        for (int o = 1; o < 8; o <<= 1) {
            int t2 = __shfl_up_sync(0xffu, u, o);
            if (tid >= o) u += t2;
        }
        wsum[tid] = u;
        if (tid == 7) sbase = atomicAdd(&g_ctr, u);
    }
    __syncthreads();
    int inc = v + (wid > 0 ? wsum[wid - 1] : 0);
    if (i < Nn) {
        int st = sbase + inc - d;
        g_row2[i]   = make_int2(st, d);
        g_cursor[i] = st;
        g_dinv[i]   = rsqrtf((float)d + 1.0f);
    }
}

// ---------------- scale g_h rows by dinv (fp32 math) ------------------------
__global__ void __launch_bounds__(256) scaleh_kernel() {
    int i = blockIdx.x * 256 + threadIdx.x;   // 16B chunk index, 8 per node
    if (i >= Nn * 8) return;
    float dv = g_dinv[i >> 3];
    int4 v = ((int4*)g_h)[i];
    __half2* h = (__half2*)&v;
    #pragma unroll
    for (int k = 0; k < 4; k++) {
        float2 f = __half22float2(h[k]);
        h[k] = __floats2half2_rn(f.x * dv, f.y * dv);
    }
    ((int4*)g_h)[i] = v;
}

// ---------------- scatter edges into CSR (4B src payload) -------------------
__global__ void __launch_bounds__(256) scatter_kernel(const void* __restrict__ ei_raw) {
    int e = blockIdx.x * 256 + threadIdx.x;
    if (e >= Ee) return;
    int s, d;
    if (g_is64) {
        const long long* p = (const long long*)ei_raw;
        s = (int)p[e]; d = (int)p[Ee + e];
    } else {
        const int* p = (const int*)ei_raw;
        s = p[e]; d = p[Ee + e];
    }
    int pos = atomicAdd(&g_cursor[d], 1);
    g_ecsr4[pos] = s;
}

// ---------------- layer-1 CSR aggregation + self-loop + b1 + BN stats -------
__device__ __forceinline__ void gat1(int sv, int lane, float& ax, float& ay) {
    float2 h = __half22float2(g_h[(size_t)sv * (HID / 2) + lane]);
    ax += h.x; ay += h.y;
}

__global__ void __launch_bounds__(256) agg1_csr_kernel(const float* __restrict__ b1) {
    int lane = threadIdx.x & 31;
    int warp = (blockIdx.x * 256 + threadIdx.x) >> 5;
    int nw   = (gridDim.x * 256) >> 5;
    float2 bb = *(const float2*)(b1 + 2 * lane);
    float2 sum = {0.f, 0.f}, sq = {0.f, 0.f};

    for (int n = warp; n < Nn; n += nw) {
        int2 rd = g_row2[n];
        int rs = rd.x, re = rd.x + rd.y;
        float ax = 0.f, ay = 0.f;
        int j = rs;
        while ((j & 3) && j < re) { gat1(g_ecsr4[j], lane, ax, ay); j++; }
        for (; j + 7 < re; j += 8) {
            int4 A = *(const int4*)(g_ecsr4 + j);
            int4 B = *(const int4*)(g_ecsr4 + j + 4);
            gat1(A.x, lane, ax, ay); gat1(A.y, lane, ax, ay);
            gat1(A.z, lane, ax, ay); gat1(A.w, lane, ax, ay);
            gat1(B.x, lane, ax, ay); gat1(B.y, lane, ax, ay);
            gat1(B.z, lane, ax, ay); gat1(B.w, lane, ax, ay);
        }
        if (j + 3 < re) {
            int4 A = *(const int4*)(g_ecsr4 + j);
            gat1(A.x, lane, ax, ay); gat1(A.y, lane, ax, ay);
            gat1(A.z, lane, ax, ay); gat1(A.w, lane, ax, ay);
            j += 4;
        }
        while (j < re) { gat1(g_ecsr4[j], lane, ax, ay); j++; }

        float dv = g_dinv[n];
        float2 hn = __half22float2(g_h[(size_t)n * (HID / 2) + lane]);  // pre-scaled
        float vx = (ax + hn.x) * dv + bb.x;
        float vy = (ay + hn.y) * dv + bb.y;
        g_agg[(size_t)n * (HID / 2) + lane] = __floats2half2_rn(vx, vy);
        sum.x += vx; sum.y += vy;
        sq.x  += vx * vx; sq.y += vy * vy;
    }

    __shared__ float ss[HID], sqs[HID];
    if (threadIdx.x < HID) { ss[threadIdx.x] = 0.f; sqs[threadIdx.x] = 0.f; }
    __syncthreads();
    atomicAdd(&ss [2 * lane],     sum.x);
    atomicAdd(&ss [2 * lane + 1], sum.y);
    atomicAdd(&sqs[2 * lane],     sq.x);
    atomicAdd(&sqs[2 * lane + 1], sq.y);
    __syncthreads();
    if (threadIdx.x < HID)          atomicAdd(&g_sum  [threadIdx.x],       ss [threadIdx.x]);
    else if (threadIdx.x < 2 * HID) atomicAdd(&g_sqsum[threadIdx.x - HID], sqs[threadIdx.x - HID]);
}

// ---------------- GEMM2 with inline BN-final + ReLU + dinv pre-scale --------
__global__ void __launch_bounds__(256) gemm2_kernel(const float* __restrict__ W2,
                                                    const float* __restrict__ gamma,
                                                    const float* __restrict__ beta) {
    __shared__ float yst[HID][68];
    __shared__ float ws [HID * OUTF];
    __shared__ float scale[HID], shift[HID];
    int tid  = threadIdx.x;
    int base = blockIdx.x * 64;
    const __half* aggh = (const __half*)g_agg;

    if (tid < HID) {
        float mean = g_sum[tid]   * (1.0f / Nn);
        float var  = g_sqsum[tid] * (1.0f / Nn) - mean * mean;
        float sc   = gamma[tid] * rsqrtf(var + 1e-5f);
        scale[tid] = sc;
        shift[tid] = beta[tid] - mean * sc;
    }
    for (int i = tid; i < HID * OUTF; i += 256) ws[i] = W2[i];
    __syncthreads();
    for (int i = tid; i < 64 * 64; i += 256) {
        int node = i >> 6, k = i & 63;
        int row = base + node;
        float v = 0.f;
        if (row < Nn) {
            v = __half2float(aggh[(size_t)row * HID + k]);
            v = fmaxf(v * scale[k] + shift[k], 0.f);
        }
        yst[k][node] = v;
    }
    __syncthreads();

    int ng = tid >> 3;
    int cg = (tid & 7) * 5;
    float acc0[5] = {}, acc1[5] = {};
    #pragma unroll 8
    for (int k = 0; k < HID; k++) {
        float2 yv = *(const float2*)&yst[k][ng * 2];
        #pragma unroll
        for (int j = 0; j < 5; j++) {
            float w = ws[k * OUTF + cg + j];
            acc0[j] += yv.x * w;
            acc1[j] += yv.y * w;
        }
    }
    int r0 = base + ng * 2;
    if (r0 < Nn) {
        float dv = g_dinv[r0];
        #pragma unroll
        for (int j = 0; j < 5; j++)
            g_h2[(size_t)r0 * OUTF + cg + j] = __float2half_rn(acc0[j] * dv);
    }
    if (r0 + 1 < Nn) {
        float dv = g_dinv[r0 + 1];
        #pragma unroll
        for (int j = 0; j < 5; j++)
            g_h2[(size_t)(r0 + 1) * OUTF + cg + j] = __float2half_rn(acc1[j] * dv);
    }
}

// ---------------- layer-2 CSR aggregation + self-loop + b2 → d_out ----------
__device__ __forceinline__ void gat2(int sv, int lane, float& ax, float& ay) {
    float2 h = __half22float2(*(const __half2*)(g_h2 + (size_t)sv * OUTF + 2 * lane));
    ax += h.x; ay += h.y;
}

__global__ void __launch_bounds__(256) agg2_csr_kernel(const float* __restrict__ b2,
                                                       float* __restrict__ out) {
    int lane = threadIdx.x & 31;
    int warp = (blockIdx.x * 256 + threadIdx.x) >> 5;
    int nw   = (gridDim.x * 256) >> 5;
    if (lane >= OUTF / 2) return;
    float2 bb = *(const float2*)(b2 + 2 * lane);

    for (int n = warp; n < Nn; n += nw) {
        int2 rd = g_row2[n];
        int rs = rd.x, re = rd.x + rd.y;
        float ax = 0.f, ay = 0.f;
        int j = rs;
        while ((j & 3) && j < re) { gat2(g_ecsr4[j], lane, ax, ay); j++; }
        for (; j + 7 < re; j += 8) {
            int4 A = *(const int4*)(g_ecsr4 + j);
            int4 B = *(const int4*)(g_ecsr4 + j + 4);
            gat2(A.x, lane, ax, ay); gat2(A.y, lane, ax, ay);
            gat2(A.z, lane, ax, ay); gat2(A.w, lane, ax, ay);
            gat2(B.x, lane, ax, ay); gat2(B.y, lane, ax, ay);
            gat2(B.z, lane, ax, ay); gat2(B.w, lane, ax, ay);
        }
        if (j + 3 < re) {
            int4 A = *(const int4*)(g_ecsr4 + j);
            gat2(A.x, lane, ax, ay); gat2(A.y, lane, ax, ay);
            gat2(A.z, lane, ax, ay); gat2(A.w, lane, ax, ay);
            j += 4;
        }
        while (j < re) { gat2(g_ecsr4[j], lane, ax, ay); j++; }

        float dv = g_dinv[n];
        float2 hn = __half22float2(*(const __half2*)(g_h2 + (size_t)n * OUTF + 2 * lane));
        float2 v = {(ax + hn.x) * dv + bb.x, (ay + hn.y) * dv + bb.y};
        *(float2*)(out + (size_t)n * OUTF + 2 * lane) = v;
    }
}

// ---------------- launch ----------------------------------------------------
extern "C" void kernel_launch(void* const* d_in, const int* in_sizes, int n_in,
                              void* d_out, int out_size) {
    const float* x     = (const float*)d_in[0];
    const void*  ei    = d_in[1];
    const float* W1    = (const float*)d_in[2];
    const float* b1    = (const float*)d_in[3];
    const float* gamma = (const float*)d_in[4];
    const float* beta  = (const float*)d_in[5];
    const float* W2    = (const float*)d_in[6];
    const float* b2    = (const float*)d_in[7];
    float* out = (float*)d_out;

    zero_kernel<<<NB, 256>>>((const int*)ei, W1);
    fused1_kernel<<<GB * 5, 256>>>(ei, x);          // gemm1 + histogram
    prep_kernel<<<NB, 256>>>();
    scaleh_kernel<<<(Nn * 8 + 255) / 256, 256>>>(); // g_h *= dinv
    scatter_kernel<<<EB, 256>>>(ei);                // 4B payload
    agg1_csr_kernel<<<AGGB, 256>>>(b1);
    gemm2_kernel<<<GB, 256>>>(W2, gamma, beta);
    agg2_csr_kernel<<<AGGB, 256>>>(b2, out);
}

// round 10
// speedup vs baseline: 1.0821x; 1.0002x over previous
#include <cuda_runtime.h>
#include <cuda_fp16.h>
#include <cstdint>

#define Nn   100000
#define Ee   1600000
#define INF  128
#define HID  64
#define OUTF 40
#define NB   ((Nn + 255) / 256)          // 391 node blocks
#define GB   ((Nn + 63) / 64)            // 1563 gemm tiles
#define EB   ((Ee + 255) / 256)          // 6250 edge blocks
#define SHB  ((Nn * 8 + 255) / 256)      // 3125 scaleh blocks
#define AGGB 1184                        // one full wave of agg blocks

// ---------------- scratch (static device globals: allocation-free) ----------
__device__ __half2 g_h  [(size_t)Nn * (HID / 2)];  // x @ W1, pre-scaled by dinv
__device__ __half2 g_agg[(size_t)Nn * (HID / 2)];  // BN input, fp16
__device__ __half  g_h2 [(size_t)Nn * OUTF];       // relu(bn)@W2, pre-scaled
__device__ __half  g_W1t[HID][INF];                // W1 transposed [n][k], fp16
__device__ float   g_dinv [Nn];
__device__ int     g_degi [Nn];
__device__ int2    g_row2 [Nn];                    // {rowstart, degree}
__device__ int     g_cursor[Nn];
__device__ int     g_ctr;
__device__ float   g_sum  [HID];
__device__ float   g_sqsum[HID];
__device__ int4    g_e4[(Ee + 3) / 4];             // 16B-aligned CSR src indices
#define g_ecsr4 ((int*)g_e4)
__device__ int     g_is64;

// ---------------- zero accumulators + dtype probe + W1 fp16 transpose -------
__global__ void __launch_bounds__(256) zero_kernel(const int* __restrict__ w,
                                                   const float* __restrict__ W1) {
    int i = blockIdx.x * 256 + threadIdx.x;
    if (i < Nn) g_degi[i] = 0;
    if (i < HID) { g_sum[i] = 0.f; g_sqsum[i] = 0.f; }
    if (i < INF * HID) {
        int n = i >> 7, k = i & 127;
        g_W1t[n][k] = __float2half_rn(W1[(size_t)k * HID + n]);
    }
    if (blockIdx.x == 0 && threadIdx.x == 0) {
        int is64 = 1;
        #pragma unroll
        for (int k = 1; k < 64; k += 2) is64 &= (w[k] == 0);
        g_is64 = is64;
        g_ctr = 0;
    }
}

// ---------------- fp16 mma helper -------------------------------------------
__device__ __forceinline__ void mma_f16(float* d, uint32_t a0, uint32_t a1,
                                        uint32_t a2, uint32_t a3,
                                        uint32_t b0, uint32_t b1) {
    asm volatile(
        "mma.sync.aligned.m16n8k16.row.col.f32.f16.f16.f32 "
        "{%0,%1,%2,%3}, {%4,%5,%6,%7}, {%8,%9}, {%0,%1,%2,%3};"
        : "+f"(d[0]), "+f"(d[1]), "+f"(d[2]), "+f"(d[3])
        : "r"(a0), "r"(a1), "r"(a2), "r"(a3), "r"(b0), "r"(b1));
}

// ---------------- fused: GEMM1 (fp16 mma) + degree histogram ----------------
// bid % 5 == 0 -> gemm tile (bid/5), else histogram block (fire-and-forget RED).
__global__ void __launch_bounds__(256) fused1_kernel(const void* __restrict__ ei_raw,
                                                     const float* __restrict__ x) {
    __shared__ __half xh [64][136];
    __shared__ __half whT[64][136];
    int bid = blockIdx.x;
    int q = bid / 5, r = bid - q * 5;
    int tid = threadIdx.x;

    if (r != 0) {
        int e = (q * 4 + (r - 1)) * 256 + tid;
        if (e < Ee) {
            int d;
            if (g_is64) d = (int)((const long long*)ei_raw)[Ee + e];
            else        d = ((const int*)ei_raw)[Ee + e];
            atomicAdd(&g_degi[d], 1);
        }
        return;
    }

    int base = q * 64;
    int lane = tid & 31, w = tid >> 5;
    int wr = (w & 3) * 16;
    int wc = (w >> 2) * 32;
    int g  = lane >> 2, t = lane & 3;

    #pragma unroll
    for (int f = 0; f < 8; f++) {
        int fi  = f * 256 + tid;
        int row = fi >> 5, kb = (fi & 31) << 2;
        float4 v = {0.f, 0.f, 0.f, 0.f};
        if (base + row < Nn) v = *(const float4*)(x + (size_t)(base + row) * INF + kb);
        __half2* dst = (__half2*)&xh[row][kb];
        dst[0] = __floats2half2_rn(v.x, v.y);
        dst[1] = __floats2half2_rn(v.z, v.w);
    }
    #pragma unroll
    for (int f = 0; f < 4; f++) {
        int fi = f * 256 + tid;
        int n = fi >> 4, kb = (fi & 15) << 3;
        *(int4*)&whT[n][kb] = *(const int4*)&g_W1t[n][kb];
    }
    __syncthreads();

    float acc[4][4] = {};
    #pragma unroll
    for (int ks = 0; ks < INF; ks += 16) {
        uint32_t a0 = *(const uint32_t*)&xh[wr + g    ][ks + 2 * t    ];
        uint32_t a1 = *(const uint32_t*)&xh[wr + g + 8][ks + 2 * t    ];
        uint32_t a2 = *(const uint32_t*)&xh[wr + g    ][ks + 2 * t + 8];
        uint32_t a3 = *(const uint32_t*)&xh[wr + g + 8][ks + 2 * t + 8];
        #pragma unroll
        for (int j = 0; j < 4; j++) {
            int n0 = wc + 8 * j;
            uint32_t b0 = *(const uint32_t*)&whT[n0 + g][ks + 2 * t    ];
            uint32_t b1 = *(const uint32_t*)&whT[n0 + g][ks + 2 * t + 8];
            mma_f16(acc[j], a0, a1, a2, a3, b0, b1);
        }
    }
    #pragma unroll
    for (int j = 0; j < 4; j++) {
        int hc = (wc + 8 * j) / 2 + t;
        int r0 = base + wr + g;
        int r1 = r0 + 8;
        if (r0 < Nn) g_h[(size_t)r0 * (HID / 2) + hc] = __floats2half2_rn(acc[j][0], acc[j][1]);
        if (r1 < Nn) g_h[(size_t)r1 * (HID / 2) + hc] = __floats2half2_rn(acc[j][2], acc[j][3]);
    }
}

// ---------------- prep: unordered CSR row assignment + dinv -----------------
__global__ void __launch_bounds__(256) prep_kernel() {
    int i = blockIdx.x * 256 + threadIdx.x;
    int tid = threadIdx.x;
    int d = (i < Nn) ? g_degi[i] : 0;
    int lane = tid & 31, wid = tid >> 5;
    int v = d;
    #pragma unroll
    for (int o = 1; o < 32; o <<= 1) {
        int u = __shfl_up_sync(0xffffffffu, v, o);
        if (lane >= o) v += u;
    }
    __shared__ int wsum[8];
    __shared__ int sbase;
    if (lane == 31) wsum[wid] = v;
    __syncthreads();
    if (tid < 8) {
        int u = wsum[tid];
        #pragma unroll
        for (int o = 1; o < 8; o <<= 1) {
            int t2 = __shfl_up_sync(0xffu, u, o);
            if (tid >= o) u += t2;
        }
        wsum[tid] = u;
        if (tid == 7) sbase = atomicAdd(&g_ctr, u);
    }
    __syncthreads();
    int inc = v + (wid > 0 ? wsum[wid - 1] : 0);
    if (i < Nn) {
        int st = sbase + inc - d;
        g_row2[i]   = make_int2(st, d);
        g_cursor[i] = st;
        g_dinv[i]   = rsqrtf((float)d + 1.0f);
    }
}

// ---------------- fused: scale g_h by dinv + scatter edges into CSR ---------
// blocks [0, SHB): scaleh; blocks [SHB, SHB+EB): scatter.
__global__ void __launch_bounds__(256) scatscale_kernel(const void* __restrict__ ei_raw) {
    int bid = blockIdx.x;
    int tid = threadIdx.x;

    if (bid < SHB) {
        int i = bid * 256 + tid;             // 16B chunk index, 8 per node
        if (i >= Nn * 8) return;
        float dv = g_dinv[i >> 3];
        int4 v = ((int4*)g_h)[i];
        __half2* h = (__half2*)&v;
        #pragma unroll
        for (int k = 0; k < 4; k++) {
            float2 f = __half22float2(h[k]);
            h[k] = __floats2half2_rn(f.x * dv, f.y * dv);
        }
        ((int4*)g_h)[i] = v;
        return;
    }

    int e = (bid - SHB) * 256 + tid;
    if (e >= Ee) return;
    int s, d;
    if (g_is64) {
        const long long* p = (const long long*)ei_raw;
        s = (int)p[e]; d = (int)p[Ee + e];
    } else {
        const int* p = (const int*)ei_raw;
        s = p[e]; d = p[Ee + e];
    }
    int pos = atomicAdd(&g_cursor[d], 1);
    g_ecsr4[pos] = s;
}

// ---------------- layer-1 CSR aggregation + self-loop + b1 + BN stats -------
__device__ __forceinline__ void gat1(int sv, int lane, float& ax, float& ay) {
    float2 h = __half22float2(g_h[(size_t)sv * (HID / 2) + lane]);
    ax += h.x; ay += h.y;
}

__global__ void __launch_bounds__(256) agg1_csr_kernel(const float* __restrict__ b1) {
    int lane = threadIdx.x & 31;
    int warp = (blockIdx.x * 256 + threadIdx.x) >> 5;
    int nw   = (gridDim.x * 256) >> 5;
    float2 bb = *(const float2*)(b1 + 2 * lane);
    float2 sum = {0.f, 0.f}, sq = {0.f, 0.f};

    for (int n = warp; n < Nn; n += nw) {
        int2 rd = g_row2[n];
        int rs = rd.x, re = rd.x + rd.y;
        float ax = 0.f, ay = 0.f;
        int j = rs;
        while ((j & 3) && j < re) { gat1(g_ecsr4[j], lane, ax, ay); j++; }
        for (; j + 15 < re; j += 16) {     // 16 gathers in flight
            int4 A = *(const int4*)(g_ecsr4 + j);
            int4 B = *(const int4*)(g_ecsr4 + j + 4);
            int4 C = *(const int4*)(g_ecsr4 + j + 8);
            int4 D = *(const int4*)(g_ecsr4 + j + 12);
            gat1(A.x, lane, ax, ay); gat1(A.y, lane, ax, ay);
            gat1(A.z, lane, ax, ay); gat1(A.w, lane, ax, ay);
            gat1(B.x, lane, ax, ay); gat1(B.y, lane, ax, ay);
            gat1(B.z, lane, ax, ay); gat1(B.w, lane, ax, ay);
            gat1(C.x, lane, ax, ay); gat1(C.y, lane, ax, ay);
            gat1(C.z, lane, ax, ay); gat1(C.w, lane, ax, ay);
            gat1(D.x, lane, ax, ay); gat1(D.y, lane, ax, ay);
            gat1(D.z, lane, ax, ay); gat1(D.w, lane, ax, ay);
        }
        for (; j + 7 < re; j += 8) {
            int4 A = *(const int4*)(g_ecsr4 + j);
            int4 B = *(const int4*)(g_ecsr4 + j + 4);
            gat1(A.x, lane, ax, ay); gat1(A.y, lane, ax, ay);
            gat1(A.z, lane, ax, ay); gat1(A.w, lane, ax, ay);
            gat1(B.x, lane, ax, ay); gat1(B.y, lane, ax, ay);
            gat1(B.z, lane, ax, ay); gat1(B.w, lane, ax, ay);
        }
        if (j + 3 < re) {
            int4 A = *(const int4*)(g_ecsr4 + j);
            gat1(A.x, lane, ax, ay); gat1(A.y, lane, ax, ay);
            gat1(A.z, lane, ax, ay); gat1(A.w, lane, ax, ay);
            j += 4;
        }
        while (j < re) { gat1(g_ecsr4[j], lane, ax, ay); j++; }

        float dv = g_dinv[n];
        float2 hn = __half22float2(g_h[(size_t)n * (HID / 2) + lane]);  // pre-scaled
        float vx = (ax + hn.x) * dv + bb.x;
        float vy = (ay + hn.y) * dv + bb.y;
        g_agg[(size_t)n * (HID / 2) + lane] = __floats2half2_rn(vx, vy);
        sum.x += vx; sum.y += vy;
        sq.x  += vx * vx; sq.y += vy * vy;
    }

    __shared__ float ss[HID], sqs[HID];
    if (threadIdx.x < HID) { ss[threadIdx.x] = 0.f; sqs[threadIdx.x] = 0.f; }
    __syncthreads();
    atomicAdd(&ss [2 * lane],     sum.x);
    atomicAdd(&ss [2 * lane + 1], sum.y);
    atomicAdd(&sqs[2 * lane],     sq.x);
    atomicAdd(&sqs[2 * lane + 1], sq.y);
    __syncthreads();
    if (threadIdx.x < HID)          atomicAdd(&g_sum  [threadIdx.x],       ss [threadIdx.x]);
    else if (threadIdx.x < 2 * HID) atomicAdd(&g_sqsum[threadIdx.x - HID], sqs[threadIdx.x - HID]);
}

// ---------------- GEMM2 with inline BN-final + ReLU + dinv pre-scale --------
__global__ void __launch_bounds__(256) gemm2_kernel(const float* __restrict__ W2,
                                                    const float* __restrict__ gamma,
                                                    const float* __restrict__ beta) {
    __shared__ float yst[HID][68];
    __shared__ float ws [HID * OUTF];
    __shared__ float scale[HID], shift[HID];
    int tid  = threadIdx.x;
    int base = blockIdx.x * 64;
    const __half* aggh = (const __half*)g_agg;

    if (tid < HID) {
        float mean = g_sum[tid]   * (1.0f / Nn);
        float var  = g_sqsum[tid] * (1.0f / Nn) - mean * mean;
        float sc   = gamma[tid] * rsqrtf(var + 1e-5f);
        scale[tid] = sc;
        shift[tid] = beta[tid] - mean * sc;
    }
    for (int i = tid; i < HID * OUTF; i += 256) ws[i] = W2[i];
    __syncthreads();
    for (int i = tid; i < 64 * 64; i += 256) {
        int node = i >> 6, k = i & 63;
        int row = base + node;
        float v = 0.f;
        if (row < Nn) {
            v = __half2float(aggh[(size_t)row * HID + k]);
            v = fmaxf(v * scale[k] + shift[k], 0.f);
        }
        yst[k][node] = v;
    }
    __syncthreads();

    int ng = tid >> 3;
    int cg = (tid & 7) * 5;
    float acc0[5] = {}, acc1[5] = {};
    #pragma unroll 8
    for (int k = 0; k < HID; k++) {
        float2 yv = *(const float2*)&yst[k][ng * 2];
        #pragma unroll
        for (int j = 0; j < 5; j++) {
            float w = ws[k * OUTF + cg + j];
            acc0[j] += yv.x * w;
            acc1[j] += yv.y * w;
        }
    }
    int r0 = base + ng * 2;
    if (r0 < Nn) {
        float dv = g_dinv[r0];
        #pragma unroll
        for (int j = 0; j < 5; j++)
            g_h2[(size_t)r0 * OUTF + cg + j] = __float2half_rn(acc0[j] * dv);
    }
    if (r0 + 1 < Nn) {
        float dv = g_dinv[r0 + 1];
        #pragma unroll
        for (int j = 0; j < 5; j++)
            g_h2[(size_t)(r0 + 1) * OUTF + cg + j] = __float2half_rn(acc1[j] * dv);
    }
}

// ---------------- layer-2 CSR aggregation + self-loop + b2 → d_out ----------
__device__ __forceinline__ void gat2(int sv, int lane, float& ax, float& ay) {
    float2 h = __half22float2(*(const __half2*)(g_h2 + (size_t)sv * OUTF + 2 * lane));
    ax += h.x; ay += h.y;
}

__global__ void __launch_bounds__(256) agg2_csr_kernel(const float* __restrict__ b2,
                                                       float* __restrict__ out) {
    int lane = threadIdx.x & 31;
    int warp = (blockIdx.x * 256 + threadIdx.x) >> 5;
    int nw   = (gridDim.x * 256) >> 5;
    if (lane >= OUTF / 2) return;
    float2 bb = *(const float2*)(b2 + 2 * lane);

    for (int n = warp; n < Nn; n += nw) {
        int2 rd = g_row2[n];
        int rs = rd.x, re = rd.x + rd.y;
        float ax = 0.f, ay = 0.f;
        int j = rs;
        while ((j & 3) && j < re) { gat2(g_ecsr4[j], lane, ax, ay); j++; }
        for (; j + 7 < re; j += 8) {
            int4 A = *(const int4*)(g_ecsr4 + j);
            int4 B = *(const int4*)(g_ecsr4 + j + 4);
            gat2(A.x, lane, ax, ay); gat2(A.y, lane, ax, ay);
            gat2(A.z, lane, ax, ay); gat2(A.w, lane, ax, ay);
            gat2(B.x, lane, ax, ay); gat2(B.y, lane, ax, ay);
            gat2(B.z, lane, ax, ay); gat2(B.w, lane, ax, ay);
        }
        if (j + 3 < re) {
            int4 A = *(const int4*)(g_ecsr4 + j);
            gat2(A.x, lane, ax, ay); gat2(A.y, lane, ax, ay);
            gat2(A.z, lane, ax, ay); gat2(A.w, lane, ax, ay);
            j += 4;
        }
        while (j < re) { gat2(g_ecsr4[j], lane, ax, ay); j++; }

        float dv = g_dinv[n];
        float2 hn = __half22float2(*(const __half2*)(g_h2 + (size_t)n * OUTF + 2 * lane));
        float2 v = {(ax + hn.x) * dv + bb.x, (ay + hn.y) * dv + bb.y};
        *(float2*)(out + (size_t)n * OUTF + 2 * lane) = v;
    }
}

// ---------------- launch ----------------------------------------------------
extern "C" void kernel_launch(void* const* d_in, const int* in_sizes, int n_in,
                              void* d_out, int out_size) {
    const float* x     = (const float*)d_in[0];
    const void*  ei    = d_in[1];
    const float* W1    = (const float*)d_in[2];
    const float* b1    = (const float*)d_in[3];
    const float* gamma = (const float*)d_in[4];
    const float* beta  = (const float*)d_in[5];
    const float* W2    = (const float*)d_in[6];
    const float* b2    = (const float*)d_in[7];
    float* out = (float*)d_out;

    zero_kernel<<<NB, 256>>>((const int*)ei, W1);
    fused1_kernel<<<GB * 5, 256>>>(ei, x);          // gemm1 + histogram
    prep_kernel<<<NB, 256>>>();
    scatscale_kernel<<<SHB + EB, 256>>>(ei);        // scaleh + scatter fused
    agg1_csr_kernel<<<AGGB, 256>>>(b1);
    gemm2_kernel<<<GB, 256>>>(W2, gamma, beta);
    agg2_csr_kernel<<<AGGB, 256>>>(b2, out);
}